// round 1
// baseline (speedup 1.0000x reference)
#include <cuda_runtime.h>
#include <math.h>

#define BATCH 4096
#define HID 512
#define SEQLEN 7
#define FEAT 160
#define G4 2048          // 4*HID
#define NCLS 256

// ---------------- scratch (device globals: no allocation allowed) ----------
__device__ __align__(16) float d_pool1[BATCH * 9 * 26 * 10];      // 38 MB
__device__ __align__(16) float d_seq[BATCH * SEQLEN * FEAT];      // 18 MB
__device__ __align__(16) float d_zx[BATCH * SEQLEN * G4];         // 235 MB
__device__ __align__(16) float d_z[BATCH * G4];                   // 33 MB
__device__ __align__(16) float d_cat[BATCH * 1024];               // h1|h2
__device__ __align__(16) float d_c1[BATCH * HID];
__device__ __align__(16) float d_c2[BATCH * HID];
__device__ __align__(16) float d_wcat[1024 * G4];                 // [W2;U2]

// ---------------- utility ---------------------------------------------------
__global__ void zero_kernel(float* __restrict__ p, int n) {
    int i = blockIdx.x * blockDim.x + threadIdx.x;
    if (i < n) p[i] = 0.0f;
}

__global__ void build_wcat(const float* __restrict__ W2,
                           const float* __restrict__ U2,
                           float* __restrict__ wcat) {
    int i = blockIdx.x * blockDim.x + threadIdx.x;  // over 1024*2048
    int row = i >> 11;           // /2048
    int col = i & 2047;
    wcat[i] = (row < HID) ? W2[row * G4 + col] : U2[(row - HID) * G4 + col];
}

// ---------------- conv1 + relu + maxpool(w=3,s=3) --------------------------
// x: [B,15,80,3], w: [7,3,3,10], out: [B,9,26,10]
__global__ __launch_bounds__(256) void conv1_pool(
    const float* __restrict__ x, const float* __restrict__ w,
    const float* __restrict__ bias, float* __restrict__ out) {
    __shared__ float sIn[7 * 80 * 3];   // 1680
    __shared__ float sW[7 * 3 * 3 * 10];// 630
    int br = blockIdx.x;                // b*9 + r
    int r = br % 9;
    int b = br / 9;
    const float* xr = x + ((size_t)(b * 15 + r) * 80) * 3;  // rows r..r+6 contiguous
    for (int i = threadIdx.x; i < 1680; i += blockDim.x) sIn[i] = xr[i];
    for (int i = threadIdx.x; i < 630; i += blockDim.x) sW[i] = w[i];
    __syncthreads();

    for (int item = threadIdx.x; item < 260; item += blockDim.x) {
        int p = item / 10;   // pooled col 0..25
        int co = item % 10;
        float best = -1e30f;
#pragma unroll
        for (int dx = 0; dx < 3; dx++) {
            int cw = p * 3 + dx;
            float acc = 0.0f;
#pragma unroll
            for (int kh = 0; kh < 7; kh++)
#pragma unroll
                for (int kw = 0; kw < 3; kw++)
#pragma unroll
                    for (int ci = 0; ci < 3; ci++)
                        acc += sIn[kh * 240 + (cw + kw) * 3 + ci] *
                               sW[((kh * 3 + kw) * 3 + ci) * 10 + co];
            best = fmaxf(best, acc);
        }
        out[((size_t)br * 26 + p) * 10 + co] = fmaxf(best + bias[co], 0.0f);
    }
}

// ---------------- conv2 + relu + maxpool(w=3,s=3) -> seq --------------------
// in: [B,9,26,10], w: [3,3,10,20], seq: [B,7,160] (feature = pw*20 + co)
__global__ __launch_bounds__(256) void conv2_pool(
    const float* __restrict__ in, const float* __restrict__ w,
    const float* __restrict__ bias, float* __restrict__ seq) {
    __shared__ float sIn[3 * 26 * 10];    // 780
    __shared__ float sW[3 * 3 * 10 * 20]; // 1800
    int br = blockIdx.x;                  // b*7 + r
    int r = br % 7;
    int b = br / 7;
    const float* inr = in + ((size_t)(b * 9 + r) * 26) * 10;  // rows r..r+2 contiguous
    for (int i = threadIdx.x; i < 780; i += blockDim.x) sIn[i] = inr[i];
    for (int i = threadIdx.x; i < 1800; i += blockDim.x) sW[i] = w[i];
    __syncthreads();

    for (int item = threadIdx.x; item < 160; item += blockDim.x) {
        int p = item / 20;   // pooled col 0..7
        int co = item % 20;
        float best = -1e30f;
#pragma unroll
        for (int dx = 0; dx < 3; dx++) {
            int cw = p * 3 + dx;
            float acc = 0.0f;
#pragma unroll
            for (int kh = 0; kh < 3; kh++)
#pragma unroll
                for (int kw = 0; kw < 3; kw++)
#pragma unroll
                    for (int ci = 0; ci < 10; ci++)
                        acc += sIn[kh * 260 + (cw + kw) * 10 + ci] *
                               sW[((kh * 3 + kw) * 10 + ci) * 20 + co];
            best = fmaxf(best, acc);
        }
        seq[(size_t)br * 160 + p * 20 + co] = fmaxf(best + bias[co], 0.0f);
    }
}

// ---------------- generic fp32 GEMM: C = A@B (+Cadd) (+bias) (relu) --------
// A [M,K] lda, B [K,N] ldb, C [M,N] ldc. Requires M%128==0, N%128==0, K%16==0.
#define TBM 128
#define TBN 128
#define TBK 16

__global__ __launch_bounds__(256) void gemm_f32(
    int M, int N, int K,
    const float* __restrict__ A, int lda,
    const float* __restrict__ B, int ldb,
    float* __restrict__ C, int ldc,
    const float* __restrict__ Cadd, int ldca,
    const float* __restrict__ bias, int relu) {
    __shared__ float As[2][TBK][TBM];
    __shared__ float Bs[2][TBK][TBN];

    int tid = threadIdx.x;
    int bm = blockIdx.y * TBM;
    int bn = blockIdx.x * TBN;

    // global->smem mapping
    int a_row = tid >> 2;           // 0..63 (+64 for second)
    int a_k   = (tid & 3) * 4;      // 0,4,8,12
    int b_k   = tid >> 5;           // 0..7 (+8 for second)
    int b_n   = (tid & 31) * 4;     // 0..124

    // compute mapping: 4+4 split in each dim
    int ra = (tid >> 4) * 4;        // 0..60
    int cb = (tid & 15) * 4;        // 0..60

    const float* Ag = A + (size_t)bm * lda;
    const float* Bg = B + bn;

    float acc[8][8];
#pragma unroll
    for (int i = 0; i < 8; i++)
#pragma unroll
        for (int j = 0; j < 8; j++) acc[i][j] = 0.0f;

    float4 pa0, pa1, pb0, pb1;

    // prologue
    pa0 = *(const float4*)(Ag + (size_t)a_row * lda + a_k);
    pa1 = *(const float4*)(Ag + (size_t)(a_row + 64) * lda + a_k);
    pb0 = *(const float4*)(Bg + (size_t)b_k * ldb + b_n);
    pb1 = *(const float4*)(Bg + (size_t)(b_k + 8) * ldb + b_n);
    {
        As[0][a_k + 0][a_row] = pa0.x; As[0][a_k + 1][a_row] = pa0.y;
        As[0][a_k + 2][a_row] = pa0.z; As[0][a_k + 3][a_row] = pa0.w;
        As[0][a_k + 0][a_row + 64] = pa1.x; As[0][a_k + 1][a_row + 64] = pa1.y;
        As[0][a_k + 2][a_row + 64] = pa1.z; As[0][a_k + 3][a_row + 64] = pa1.w;
        *(float4*)&Bs[0][b_k][b_n] = pb0;
        *(float4*)&Bs[0][b_k + 8][b_n] = pb1;
    }
    __syncthreads();

    int nk = K / TBK;
    for (int kt = 0; kt < nk; kt++) {
        int buf = kt & 1;
        if (kt + 1 < nk) {
            int k0 = (kt + 1) * TBK;
            pa0 = *(const float4*)(Ag + (size_t)a_row * lda + k0 + a_k);
            pa1 = *(const float4*)(Ag + (size_t)(a_row + 64) * lda + k0 + a_k);
            pb0 = *(const float4*)(Bg + (size_t)(k0 + b_k) * ldb + b_n);
            pb1 = *(const float4*)(Bg + (size_t)(k0 + b_k + 8) * ldb + b_n);
        }
#pragma unroll
        for (int kk = 0; kk < TBK; kk++) {
            float a[8], bb[8];
            *(float4*)(a)     = *(const float4*)&As[buf][kk][ra];
            *(float4*)(a + 4) = *(const float4*)&As[buf][kk][ra + 64];
            *(float4*)(bb)     = *(const float4*)&Bs[buf][kk][cb];
            *(float4*)(bb + 4) = *(const float4*)&Bs[buf][kk][cb + 64];
#pragma unroll
            for (int i = 0; i < 8; i++)
#pragma unroll
                for (int j = 0; j < 8; j++)
                    acc[i][j] += a[i] * bb[j];
        }
        if (kt + 1 < nk) {
            int nb = buf ^ 1;
            As[nb][a_k + 0][a_row] = pa0.x; As[nb][a_k + 1][a_row] = pa0.y;
            As[nb][a_k + 2][a_row] = pa0.z; As[nb][a_k + 3][a_row] = pa0.w;
            As[nb][a_k + 0][a_row + 64] = pa1.x; As[nb][a_k + 1][a_row + 64] = pa1.y;
            As[nb][a_k + 2][a_row + 64] = pa1.z; As[nb][a_k + 3][a_row + 64] = pa1.w;
            *(float4*)&Bs[nb][b_k][b_n] = pb0;
            *(float4*)&Bs[nb][b_k + 8][b_n] = pb1;
        }
        __syncthreads();
    }

    // epilogue
#pragma unroll
    for (int i = 0; i < 8; i++) {
        int row = bm + ra + ((i < 4) ? i : 60 + i);  // ra+i or ra+64+(i-4)
#pragma unroll
        for (int j = 0; j < 8; j++) {
            int col = bn + cb + ((j < 4) ? j : 60 + j);
            float v = acc[i][j];
            if (Cadd) v += Cadd[(size_t)row * ldca + col];
            if (bias) v += bias[col];
            if (relu) v = fmaxf(v, 0.0f);
            C[(size_t)row * ldc + col] = v;
        }
    }
}

// ---------------- LSTM gate elementwise -------------------------------------
__device__ __forceinline__ float sigmoidf_(float x) {
    return 1.0f / (1.0f + expf(-x));
}

__global__ void lstm_gate(const float* __restrict__ z,
                          const float* __restrict__ bias,
                          float* __restrict__ c,
                          float* __restrict__ cat_h, int hoff) {
    int idx = blockIdx.x * blockDim.x + threadIdx.x;   // 0..BATCH*HID
    if (idx >= BATCH * HID) return;
    int b = idx >> 9;        // /512
    int j = idx & 511;
    const float* zr = z + (size_t)b * G4;
    float gi = zr[j]            + bias[j];
    float gf = zr[j + HID]      + bias[j + HID];
    float gg = zr[j + 2 * HID]  + bias[j + 2 * HID];
    float go = zr[j + 3 * HID]  + bias[j + 3 * HID];
    float cv = sigmoidf_(gf) * c[idx] + sigmoidf_(gi) * tanhf(gg);
    c[idx] = cv;
    cat_h[(size_t)b * 1024 + hoff + j] = sigmoidf_(go) * tanhf(cv);
}

// ---------------- launch -----------------------------------------------------
extern "C" void kernel_launch(void* const* d_in, const int* in_sizes, int n_in,
                              void* d_out, int out_size) {
    const float* x   = (const float*)d_in[0];
    const float* c1w = (const float*)d_in[1];
    const float* c1b = (const float*)d_in[2];
    const float* c2w = (const float*)d_in[3];
    const float* c2b = (const float*)d_in[4];
    const float* W1  = (const float*)d_in[5];
    const float* U1  = (const float*)d_in[6];
    const float* b1  = (const float*)d_in[7];
    const float* W2  = (const float*)d_in[8];
    const float* U2  = (const float*)d_in[9];
    const float* b2  = (const float*)d_in[10];
    const float* fcw = (const float*)d_in[11];
    const float* fcb = (const float*)d_in[12];
    float* out = (float*)d_out;

    float *pool1, *seq, *zx, *z, *cat, *c1, *c2, *wcat;
    cudaGetSymbolAddress((void**)&pool1, d_pool1);
    cudaGetSymbolAddress((void**)&seq,   d_seq);
    cudaGetSymbolAddress((void**)&zx,    d_zx);
    cudaGetSymbolAddress((void**)&z,     d_z);
    cudaGetSymbolAddress((void**)&cat,   d_cat);
    cudaGetSymbolAddress((void**)&c1,    d_c1);
    cudaGetSymbolAddress((void**)&c2,    d_c2);
    cudaGetSymbolAddress((void**)&wcat,  d_wcat);

    // init recurrent state
    zero_kernel<<<(BATCH * 1024 + 255) / 256, 256>>>(cat, BATCH * 1024);
    zero_kernel<<<(BATCH * HID + 255) / 256, 256>>>(c1, BATCH * HID);
    zero_kernel<<<(BATCH * HID + 255) / 256, 256>>>(c2, BATCH * HID);
    build_wcat<<<(1024 * G4) / 256, 256>>>(W2, U2, wcat);

    // CNN front-end
    conv1_pool<<<BATCH * 9, 256>>>(x, c1w, c1b, pool1);
    conv2_pool<<<BATCH * 7, 256>>>(pool1, c2w, c2b, seq);

    // precompute x@W1 for all timesteps: [B*7,160]@[160,2048]
    {
        dim3 g(G4 / TBN, (BATCH * SEQLEN) / TBM);
        gemm_f32<<<g, 256>>>(BATCH * SEQLEN, G4, FEAT, seq, FEAT, W1, G4,
                             zx, G4, nullptr, 0, nullptr, 0);
    }

    dim3 ga(G4 / TBN, BATCH / TBM);
    for (int t = 0; t < SEQLEN; t++) {
        // layer 1: z = zx[t] + h1@U1
        gemm_f32<<<ga, 256>>>(BATCH, G4, HID, cat, 1024, U1, G4,
                              z, G4, zx + t * G4, SEQLEN * G4, nullptr, 0);
        lstm_gate<<<(BATCH * HID) / 256, 256>>>(z, b1, c1, cat, 0);
        // layer 2: z = [h1|h2] @ [W2;U2]
        gemm_f32<<<ga, 256>>>(BATCH, G4, 1024, cat, 1024, wcat, G4,
                              z, G4, nullptr, 0, nullptr, 0);
        lstm_gate<<<(BATCH * HID) / 256, 256>>>(z, b2, c2, cat, HID);
    }

    // FC head: relu(h2 @ fc_w + fc_b)
    {
        dim3 gf(NCLS / TBN, BATCH / TBM);
        gemm_f32<<<gf, 256>>>(BATCH, NCLS, HID, cat + HID, 1024, fcw, NCLS,
                              out, NCLS, nullptr, 0, fcb, 1);
    }
}

// round 3
// speedup vs baseline: 2.2751x; 2.2751x over previous
#include <cuda_runtime.h>
#include <cuda_bf16.h>
#include <cstdint>
#include <math.h>

#define BATCH 4096
#define HID 512
#define SEQLEN 7
#define FEATP 192            // padded feature dim (160 -> 192)
#define G4 2048              // 4*HID
#define NCLS 256
#define BT (BATCH * SEQLEN)  // 28672

// ---------------------------------------------------------------------------
// scratch (device globals)
// ---------------------------------------------------------------------------
__device__ __align__(16) float d_pool1[BATCH * 9 * 26 * 10];
__device__ __align__(16) __nv_bfloat16 d_seq_hi[BT * FEATP];
__device__ __align__(16) __nv_bfloat16 d_seq_lo[BT * FEATP];
__device__ __align__(16) float d_zx[BT * G4];
__device__ __align__(16) float d_z[BATCH * G4];
__device__ __align__(16) __nv_bfloat16 d_cat_hi[BATCH * 1024];
__device__ __align__(16) __nv_bfloat16 d_cat_lo[BATCH * 1024];
__device__ __align__(16) float d_c1[BATCH * HID];
__device__ __align__(16) float d_c2[BATCH * HID];
__device__ __align__(16) __nv_bfloat16 d_W1t_hi[G4 * FEATP];
__device__ __align__(16) __nv_bfloat16 d_W1t_lo[G4 * FEATP];
__device__ __align__(16) __nv_bfloat16 d_U1t_hi[G4 * HID];
__device__ __align__(16) __nv_bfloat16 d_U1t_lo[G4 * HID];
__device__ __align__(16) __nv_bfloat16 d_WCt_hi[G4 * 1024];
__device__ __align__(16) __nv_bfloat16 d_WCt_lo[G4 * 1024];
__device__ __align__(16) __nv_bfloat16 d_FCt_hi[NCLS * HID];
__device__ __align__(16) __nv_bfloat16 d_FCt_lo[NCLS * HID];

// ---------------------------------------------------------------------------
// utility kernels
// ---------------------------------------------------------------------------
__global__ void zero_kernel(float* __restrict__ p, int n) {
    int i = blockIdx.x * blockDim.x + threadIdx.x;
    if (i < n) p[i] = 0.0f;
}

// W [K,N] row-major -> Bt hi/lo [N, Kpad] row-major (zero padded rows k>=K)
__global__ void transpose_split(const float* __restrict__ W, int K, int N, int Kpad,
                                __nv_bfloat16* __restrict__ hi,
                                __nv_bfloat16* __restrict__ lo) {
    int i = blockIdx.x * blockDim.x + threadIdx.x;
    if (i >= N * Kpad) return;
    int n = i / Kpad, k = i % Kpad;
    float v = (k < K) ? W[(size_t)k * N + n] : 0.0f;
    __nv_bfloat16 h = __float2bfloat16(v);
    hi[i] = h;
    lo[i] = __float2bfloat16(v - __bfloat162float(h));
}

// [W2;U2] fused, transposed + split: out [2048 n][1024 k]
__global__ void build_wcatT(const float* __restrict__ W2, const float* __restrict__ U2,
                            __nv_bfloat16* __restrict__ hi, __nv_bfloat16* __restrict__ lo) {
    int i = blockIdx.x * blockDim.x + threadIdx.x;  // 2048*1024
    int n = i >> 10;
    int k = i & 1023;
    float v = (k < HID) ? W2[(size_t)k * G4 + n] : U2[(size_t)(k - HID) * G4 + n];
    __nv_bfloat16 h = __float2bfloat16(v);
    hi[i] = h;
    lo[i] = __float2bfloat16(v - __bfloat162float(h));
}

// ---------------------------------------------------------------------------
// conv1 + relu + maxpool(3,3)
// ---------------------------------------------------------------------------
__global__ __launch_bounds__(256) void conv1_pool(
    const float* __restrict__ x, const float* __restrict__ w,
    const float* __restrict__ bias, float* __restrict__ out) {
    __shared__ float sIn[7 * 80 * 3];
    __shared__ float sW[7 * 3 * 3 * 10];
    int br = blockIdx.x;
    int r = br % 9;
    int b = br / 9;
    const float* xr = x + ((size_t)(b * 15 + r) * 80) * 3;
    for (int i = threadIdx.x; i < 1680; i += blockDim.x) sIn[i] = xr[i];
    for (int i = threadIdx.x; i < 630; i += blockDim.x) sW[i] = w[i];
    __syncthreads();
    for (int item = threadIdx.x; item < 260; item += blockDim.x) {
        int p = item / 10, co = item % 10;
        float best = -1e30f;
#pragma unroll
        for (int dx = 0; dx < 3; dx++) {
            int cw = p * 3 + dx;
            float acc = 0.0f;
#pragma unroll
            for (int kh = 0; kh < 7; kh++)
#pragma unroll
                for (int kw = 0; kw < 3; kw++)
#pragma unroll
                    for (int ci = 0; ci < 3; ci++)
                        acc += sIn[kh * 240 + (cw + kw) * 3 + ci] *
                               sW[((kh * 3 + kw) * 3 + ci) * 10 + co];
            best = fmaxf(best, acc);
        }
        out[((size_t)br * 26 + p) * 10 + co] = fmaxf(best + bias[co], 0.0f);
    }
}

// ---------------------------------------------------------------------------
// conv2 + relu + maxpool(3,3) -> seq hi/lo (padded to 192)
// ---------------------------------------------------------------------------
__global__ __launch_bounds__(256) void conv2_pool_split(
    const float* __restrict__ in, const float* __restrict__ w,
    const float* __restrict__ bias,
    __nv_bfloat16* __restrict__ shi, __nv_bfloat16* __restrict__ slo) {
    __shared__ float sIn[3 * 26 * 10];
    __shared__ float sW[3 * 3 * 10 * 20];
    int br = blockIdx.x;
    int r = br % 7;
    int b = br / 7;
    const float* inr = in + ((size_t)(b * 9 + r) * 26) * 10;
    for (int i = threadIdx.x; i < 780; i += blockDim.x) sIn[i] = inr[i];
    for (int i = threadIdx.x; i < 1800; i += blockDim.x) sW[i] = w[i];
    __syncthreads();
    for (int item = threadIdx.x; item < FEATP; item += blockDim.x) {
        float v = 0.0f;
        if (item < 160) {
            int p = item / 20, co = item % 20;
            float best = -1e30f;
#pragma unroll
            for (int dx = 0; dx < 3; dx++) {
                int cw = p * 3 + dx;
                float acc = 0.0f;
#pragma unroll
                for (int kh = 0; kh < 3; kh++)
#pragma unroll
                    for (int kw = 0; kw < 3; kw++)
#pragma unroll
                        for (int ci = 0; ci < 10; ci++)
                            acc += sIn[kh * 260 + (cw + kw) * 10 + ci] *
                                   sW[((kh * 3 + kw) * 10 + ci) * 20 + co];
                best = fmaxf(best, acc);
            }
            v = fmaxf(best + bias[co], 0.0f);
        }
        __nv_bfloat16 h = __float2bfloat16(v);
        shi[(size_t)br * FEATP + item] = h;
        slo[(size_t)br * FEATP + item] = __float2bfloat16(v - __bfloat162float(h));
    }
}

// ---------------------------------------------------------------------------
// mma.sync split-bf16 GEMM: C[M,N] = (Ahi+Alo)[M,K] @ (Bhi+Blo)^T (B stored [N,K])
// CTA tile 128x256, 8 warps (2x4), warp tile 64x64, BK=32, cp.async double buffer.
// Requires M%128==0, N%256==0, K%32==0.
// ---------------------------------------------------------------------------
#define ROWB 80                     // smem row pitch bytes (32 bf16 + 8 pad)
#define A_TILE_B (128 * ROWB)       // 10240
#define B_TILE_B (256 * ROWB)       // 20480
#define STAGE_B (2 * A_TILE_B + 2 * B_TILE_B)   // 61440
#define GSM_BYTES (2 * STAGE_B)     // 122880

__device__ __forceinline__ void cp_async8(void* saddr, const void* gaddr) {
    uint32_t sa;
    asm("{ .reg .u64 t; cvta.to.shared.u64 t, %1; cvt.u32.u64 %0, t; }" : "=r"(sa) : "l"(saddr));
    asm volatile("cp.async.ca.shared.global [%0], [%1], 8;" :: "r"(sa), "l"(gaddr) : "memory");
}

__device__ __forceinline__ void mma_bf16(float* c, const uint32_t* a, uint32_t b0, uint32_t b1) {
    asm volatile(
        "mma.sync.aligned.m16n8k16.row.col.f32.bf16.bf16.f32 "
        "{%0,%1,%2,%3}, {%4,%5,%6,%7}, {%8,%9}, {%0,%1,%2,%3};"
        : "+f"(c[0]), "+f"(c[1]), "+f"(c[2]), "+f"(c[3])
        : "r"(a[0]), "r"(a[1]), "r"(a[2]), "r"(a[3]), "r"(b0), "r"(b1));
}

__global__ __launch_bounds__(256, 1) void gemm_bf16s(
    int M, int N, int K,
    const __nv_bfloat16* __restrict__ Ahi, const __nv_bfloat16* __restrict__ Alo, int lda,
    const __nv_bfloat16* __restrict__ Bhi, const __nv_bfloat16* __restrict__ Blo, int ldb,
    float* __restrict__ C, int ldc,
    const float* __restrict__ Cadd, int ldca,
    const float* __restrict__ bias, int relu) {
    extern __shared__ char smem[];
    int tid = threadIdx.x;
    int lane = tid & 31;
    int warp = tid >> 5;
    int wm = warp >> 2;          // 0..1
    int wn = warp & 3;           // 0..3
    int gid = lane >> 2;         // 0..7
    int tig = lane & 3;          // 0..3

    int bm = blockIdx.y * 128;
    int bn = blockIdx.x * 256;

    const __nv_bfloat16* Ah0 = Ahi + (size_t)bm * lda;
    const __nv_bfloat16* Al0 = Alo + (size_t)bm * lda;
    const __nv_bfloat16* Bh0 = Bhi + (size_t)bn * ldb;
    const __nv_bfloat16* Bl0 = Blo + (size_t)bn * ldb;

    float acc[4][8][4];
#pragma unroll
    for (int i = 0; i < 4; i++)
#pragma unroll
        for (int j = 0; j < 8; j++)
#pragma unroll
            for (int r = 0; r < 4; r++) acc[i][j][r] = 0.0f;

    int nst = K >> 5;

    // ---- copy stage helper (as a lambda-like macro block) ----
#define ISSUE_STAGE(kt, buf) do {                                              \
        char* st = smem + (buf) * STAGE_B;                                     \
        int k0 = (kt) << 5;                                                    \
        _Pragma("unroll")                                                      \
        for (int i = 0; i < 4; i++) {                                          \
            int ch = tid + i * 256;                                            \
            int row = ch >> 3, cc = ch & 7;                                    \
            char* sa = st + row * ROWB + cc * 8;                               \
            cp_async8(sa,            Ah0 + (size_t)row * lda + k0 + cc * 4);   \
            cp_async8(sa + A_TILE_B, Al0 + (size_t)row * lda + k0 + cc * 4);   \
        }                                                                      \
        _Pragma("unroll")                                                      \
        for (int i = 0; i < 8; i++) {                                          \
            int ch = tid + i * 256;                                            \
            int row = ch >> 3, cc = ch & 7;                                    \
            char* sa = st + 2 * A_TILE_B + row * ROWB + cc * 8;                \
            cp_async8(sa,            Bh0 + (size_t)row * ldb + k0 + cc * 4);   \
            cp_async8(sa + B_TILE_B, Bl0 + (size_t)row * ldb + k0 + cc * 4);   \
        }                                                                      \
        asm volatile("cp.async.commit_group;" ::: "memory");                   \
    } while (0)

    ISSUE_STAGE(0, 0);

    for (int kt = 0; kt < nst; kt++) {
        int buf = kt & 1;
        if (kt + 1 < nst) {
            ISSUE_STAGE(kt + 1, buf ^ 1);
            asm volatile("cp.async.wait_group 1;" ::: "memory");
        } else {
            asm volatile("cp.async.wait_group 0;" ::: "memory");
        }
        __syncthreads();

        char* sA = smem + buf * STAGE_B;
        char* sB = sA + 2 * A_TILE_B;

#pragma unroll
        for (int k16 = 0; k16 < 32; k16 += 16) {
            // load A fragments (hi + lo) for this k16
            uint32_t a_hi[4][4], a_lo[4][4];
#pragma unroll
            for (int ma = 0; ma < 4; ma++) {
                int row = wm * 64 + ma * 16 + gid;
                int co0 = (k16 + 2 * tig) * 2;
                int co1 = (k16 + 8 + 2 * tig) * 2;
                a_hi[ma][0] = *(const uint32_t*)(sA + row * ROWB + co0);
                a_hi[ma][1] = *(const uint32_t*)(sA + (row + 8) * ROWB + co0);
                a_hi[ma][2] = *(const uint32_t*)(sA + row * ROWB + co1);
                a_hi[ma][3] = *(const uint32_t*)(sA + (row + 8) * ROWB + co1);
                a_lo[ma][0] = *(const uint32_t*)(sA + A_TILE_B + row * ROWB + co0);
                a_lo[ma][1] = *(const uint32_t*)(sA + A_TILE_B + (row + 8) * ROWB + co0);
                a_lo[ma][2] = *(const uint32_t*)(sA + A_TILE_B + row * ROWB + co1);
                a_lo[ma][3] = *(const uint32_t*)(sA + A_TILE_B + (row + 8) * ROWB + co1);
            }
#pragma unroll
            for (int na = 0; na < 8; na++) {
                int rn = wn * 64 + na * 8 + gid;
                int co0 = (k16 + 2 * tig) * 2;
                int co1 = (k16 + 8 + 2 * tig) * 2;
                uint32_t bh0 = *(const uint32_t*)(sB + rn * ROWB + co0);
                uint32_t bh1 = *(const uint32_t*)(sB + rn * ROWB + co1);
                uint32_t bl0 = *(const uint32_t*)(sB + B_TILE_B + rn * ROWB + co0);
                uint32_t bl1 = *(const uint32_t*)(sB + B_TILE_B + rn * ROWB + co1);
#pragma unroll
                for (int ma = 0; ma < 4; ma++) {
                    mma_bf16(acc[ma][na], a_hi[ma], bh0, bh1);
                    mma_bf16(acc[ma][na], a_hi[ma], bl0, bl1);
                    mma_bf16(acc[ma][na], a_lo[ma], bh0, bh1);
                }
            }
        }
        __syncthreads();
    }

    // ---- epilogue ----
#pragma unroll
    for (int ma = 0; ma < 4; ma++) {
#pragma unroll
        for (int na = 0; na < 8; na++) {
            int row0 = bm + wm * 64 + ma * 16 + gid;
            int col = bn + wn * 64 + na * 8 + 2 * tig;
            float v0 = acc[ma][na][0], v1 = acc[ma][na][1];
            float v2 = acc[ma][na][2], v3 = acc[ma][na][3];
            if (Cadd) {
                v0 += Cadd[(size_t)row0 * ldca + col];
                v1 += Cadd[(size_t)row0 * ldca + col + 1];
                v2 += Cadd[(size_t)(row0 + 8) * ldca + col];
                v3 += Cadd[(size_t)(row0 + 8) * ldca + col + 1];
            }
            if (bias) {
                float bb0 = bias[col], bb1 = bias[col + 1];
                v0 += bb0; v1 += bb1; v2 += bb0; v3 += bb1;
            }
            if (relu) {
                v0 = fmaxf(v0, 0.0f); v1 = fmaxf(v1, 0.0f);
                v2 = fmaxf(v2, 0.0f); v3 = fmaxf(v3, 0.0f);
            }
            *(float2*)(C + (size_t)row0 * ldc + col) = make_float2(v0, v1);
            *(float2*)(C + (size_t)(row0 + 8) * ldc + col) = make_float2(v2, v3);
        }
    }
#undef ISSUE_STAGE
}

// ---------------------------------------------------------------------------
// LSTM gates: writes h into cat hi/lo (bf16 split), c in fp32
// ---------------------------------------------------------------------------
__device__ __forceinline__ float sigmoidf_(float x) { return 1.0f / (1.0f + expf(-x)); }

__global__ void lstm_gate(const float* __restrict__ z, const float* __restrict__ bias,
                          float* __restrict__ c,
                          __nv_bfloat16* __restrict__ cat_hi,
                          __nv_bfloat16* __restrict__ cat_lo, int hoff) {
    int idx = blockIdx.x * blockDim.x + threadIdx.x;
    if (idx >= BATCH * HID) return;
    int b = idx >> 9;
    int j = idx & 511;
    const float* zr = z + (size_t)b * G4;
    float gi = zr[j] + bias[j];
    float gf = zr[j + HID] + bias[j + HID];
    float gg = zr[j + 2 * HID] + bias[j + 2 * HID];
    float go = zr[j + 3 * HID] + bias[j + 3 * HID];
    float cv = sigmoidf_(gf) * c[idx] + sigmoidf_(gi) * tanhf(gg);
    c[idx] = cv;
    float h = sigmoidf_(go) * tanhf(cv);
    __nv_bfloat16 hh = __float2bfloat16(h);
    size_t o = (size_t)b * 1024 + hoff + j;
    cat_hi[o] = hh;
    cat_lo[o] = __float2bfloat16(h - __bfloat162float(hh));
}

// ---------------------------------------------------------------------------
// launch
// ---------------------------------------------------------------------------
extern "C" void kernel_launch(void* const* d_in, const int* in_sizes, int n_in,
                              void* d_out, int out_size) {
    const float* x = (const float*)d_in[0];
    const float* c1w = (const float*)d_in[1];
    const float* c1b = (const float*)d_in[2];
    const float* c2w = (const float*)d_in[3];
    const float* c2b = (const float*)d_in[4];
    const float* W1 = (const float*)d_in[5];
    const float* U1 = (const float*)d_in[6];
    const float* b1 = (const float*)d_in[7];
    const float* W2 = (const float*)d_in[8];
    const float* U2 = (const float*)d_in[9];
    const float* b2 = (const float*)d_in[10];
    const float* fcw = (const float*)d_in[11];
    const float* fcb = (const float*)d_in[12];
    float* out = (float*)d_out;

    float *pool1, *zx, *z, *c1, *c2;
    __nv_bfloat16 *shi, *slo, *chi, *clo;
    __nv_bfloat16 *w1h, *w1l, *u1h, *u1l, *wch, *wcl, *fch, *fcl;
    cudaGetSymbolAddress((void**)&pool1, d_pool1);
    cudaGetSymbolAddress((void**)&zx, d_zx);
    cudaGetSymbolAddress((void**)&z, d_z);
    cudaGetSymbolAddress((void**)&c1, d_c1);
    cudaGetSymbolAddress((void**)&c2, d_c2);
    cudaGetSymbolAddress((void**)&shi, d_seq_hi);
    cudaGetSymbolAddress((void**)&slo, d_seq_lo);
    cudaGetSymbolAddress((void**)&chi, d_cat_hi);
    cudaGetSymbolAddress((void**)&clo, d_cat_lo);
    cudaGetSymbolAddress((void**)&w1h, d_W1t_hi);
    cudaGetSymbolAddress((void**)&w1l, d_W1t_lo);
    cudaGetSymbolAddress((void**)&u1h, d_U1t_hi);
    cudaGetSymbolAddress((void**)&u1l, d_U1t_lo);
    cudaGetSymbolAddress((void**)&wch, d_WCt_hi);
    cudaGetSymbolAddress((void**)&wcl, d_WCt_lo);
    cudaGetSymbolAddress((void**)&fch, d_FCt_hi);
    cudaGetSymbolAddress((void**)&fcl, d_FCt_lo);

    cudaFuncSetAttribute(gemm_bf16s, cudaFuncAttributeMaxDynamicSharedMemorySize, GSM_BYTES);

    // init state
    zero_kernel<<<(BATCH * 1024 / 2 + 255) / 256, 256>>>((float*)chi, BATCH * 1024 / 2);
    zero_kernel<<<(BATCH * 1024 / 2 + 255) / 256, 256>>>((float*)clo, BATCH * 1024 / 2);
    zero_kernel<<<(BATCH * HID + 255) / 256, 256>>>(c1, BATCH * HID);
    zero_kernel<<<(BATCH * HID + 255) / 256, 256>>>(c2, BATCH * HID);

    // weight prep: transpose + split
    transpose_split<<<(G4 * FEATP + 255) / 256, 256>>>(W1, 160, G4, FEATP, w1h, w1l);
    transpose_split<<<(G4 * HID + 255) / 256, 256>>>(U1, HID, G4, HID, u1h, u1l);
    build_wcatT<<<(G4 * 1024) / 256, 256>>>(W2, U2, wch, wcl);
    transpose_split<<<(NCLS * HID + 255) / 256, 256>>>(fcw, HID, NCLS, HID, fch, fcl);

    // CNN front-end
    conv1_pool<<<BATCH * 9, 256>>>(x, c1w, c1b, pool1);
    conv2_pool_split<<<BATCH * 7, 256>>>(pool1, c2w, c2b, shi, slo);

    // zx = seq @ W1 for all timesteps: [28672,192] x [192,2048]
    {
        dim3 g(G4 / 256, BT / 128);
        gemm_bf16s<<<g, 256, GSM_BYTES>>>(BT, G4, FEATP, shi, slo, FEATP,
                                          w1h, w1l, FEATP, zx, G4,
                                          nullptr, 0, nullptr, 0);
    }

    dim3 ga(G4 / 256, BATCH / 128);
    for (int t = 0; t < SEQLEN; t++) {
        // layer 1: z = zx[t] + h1 @ U1
        gemm_bf16s<<<ga, 256, GSM_BYTES>>>(BATCH, G4, HID, chi, clo, 1024,
                                           u1h, u1l, HID, z, G4,
                                           zx + t * G4, SEQLEN * G4, nullptr, 0);
        lstm_gate<<<(BATCH * HID) / 256, 256>>>(z, b1, c1, chi, clo, 0);
        // layer 2: z = [h1|h2] @ [W2;U2]
        gemm_bf16s<<<ga, 256, GSM_BYTES>>>(BATCH, G4, 1024, chi, clo, 1024,
                                           wch, wcl, 1024, z, G4,
                                           nullptr, 0, nullptr, 0);
        lstm_gate<<<(BATCH * HID) / 256, 256>>>(z, b2, c2, chi, clo, HID);
    }

    // FC head: relu(h2 @ fc_w + fc_b)
    {
        dim3 gf(NCLS / 256, BATCH / 128);
        gemm_bf16s<<<gf, 256, GSM_BYTES>>>(BATCH, NCLS, HID, chi + HID, clo + HID, 1024,
                                           fch, fcl, HID, out, NCLS,
                                           nullptr, 0, fcb, 1);
    }
}

// round 4
// speedup vs baseline: 2.2957x; 1.0090x over previous
#include <cuda_runtime.h>
#include <cuda_bf16.h>
#include <cstdint>
#include <math.h>

#define BATCH 4096
#define HID 512
#define SEQLEN 7
#define FEATP 192            // padded feature dim (160 -> 192)
#define G4 2048              // 4*HID
#define NCLS 256
#define BT (BATCH * SEQLEN)  // 28672

// ---------------------------------------------------------------------------
// scratch (device globals)
// ---------------------------------------------------------------------------
__device__ __align__(16) float d_pool1[BATCH * 9 * 26 * 10];
__device__ __align__(16) __nv_bfloat16 d_seq_hi[BT * FEATP];
__device__ __align__(16) __nv_bfloat16 d_seq_lo[BT * FEATP];
__device__ __align__(16) float d_zx[BT * G4];
__device__ __align__(16) float d_z[BATCH * G4];
__device__ __align__(16) __nv_bfloat16 d_cat_hi[BATCH * 1024];
__device__ __align__(16) __nv_bfloat16 d_cat_lo[BATCH * 1024];
__device__ __align__(16) float d_c1[BATCH * HID];
__device__ __align__(16) float d_c2[BATCH * HID];
__device__ __align__(16) __nv_bfloat16 d_W1t_hi[G4 * FEATP];
__device__ __align__(16) __nv_bfloat16 d_W1t_lo[G4 * FEATP];
__device__ __align__(16) __nv_bfloat16 d_U1t_hi[G4 * HID];
__device__ __align__(16) __nv_bfloat16 d_U1t_lo[G4 * HID];
__device__ __align__(16) __nv_bfloat16 d_WCt_hi[G4 * 1024];
__device__ __align__(16) __nv_bfloat16 d_WCt_lo[G4 * 1024];
__device__ __align__(16) __nv_bfloat16 d_FCt_hi[NCLS * HID];
__device__ __align__(16) __nv_bfloat16 d_FCt_lo[NCLS * HID];

// ---------------------------------------------------------------------------
// fused init: zero recurrent state (1 launch)
// ---------------------------------------------------------------------------
__global__ void init_state(uint32_t* __restrict__ chi, uint32_t* __restrict__ clo,
                           float* __restrict__ c1, float* __restrict__ c2) {
    int i = blockIdx.x * blockDim.x + threadIdx.x;  // 0..2M-1
    chi[i] = 0u;      // BATCH*1024 bf16 = 2M u32
    clo[i] = 0u;
    c1[i] = 0.0f;     // BATCH*512 = 2M floats
    c2[i] = 0.0f;
}

// ---------------------------------------------------------------------------
// fused weight prep: transpose + hi/lo split for all 4 weight mats (1 launch)
// ---------------------------------------------------------------------------
#define PREP_W1 (G4 * FEATP)
#define PREP_U1 (G4 * HID)
#define PREP_WC (G4 * 1024)
#define PREP_FC (NCLS * HID)
#define PREP_TOTAL (PREP_W1 + PREP_U1 + PREP_WC + PREP_FC)

__global__ void prep_weights(const float* __restrict__ W1, const float* __restrict__ U1,
                             const float* __restrict__ W2, const float* __restrict__ U2,
                             const float* __restrict__ FC,
                             __nv_bfloat16* __restrict__ w1h, __nv_bfloat16* __restrict__ w1l,
                             __nv_bfloat16* __restrict__ u1h, __nv_bfloat16* __restrict__ u1l,
                             __nv_bfloat16* __restrict__ wch, __nv_bfloat16* __restrict__ wcl,
                             __nv_bfloat16* __restrict__ fch, __nv_bfloat16* __restrict__ fcl) {
    int i = blockIdx.x * blockDim.x + threadIdx.x;
    if (i >= PREP_TOTAL) return;
    float v;
    __nv_bfloat16 *hi, *lo;
    int o;
    if (i < PREP_W1) {
        o = i;
        int n = o / FEATP, k = o % FEATP;
        v = (k < 160) ? W1[(size_t)k * G4 + n] : 0.0f;
        hi = w1h; lo = w1l;
    } else if (i < PREP_W1 + PREP_U1) {
        o = i - PREP_W1;
        int n = o >> 9, k = o & 511;
        v = U1[(size_t)k * G4 + n];
        hi = u1h; lo = u1l;
    } else if (i < PREP_W1 + PREP_U1 + PREP_WC) {
        o = i - PREP_W1 - PREP_U1;
        int n = o >> 10, k = o & 1023;
        v = (k < HID) ? W2[(size_t)k * G4 + n] : U2[(size_t)(k - HID) * G4 + n];
        hi = wch; lo = wcl;
    } else {
        o = i - PREP_W1 - PREP_U1 - PREP_WC;
        int n = o >> 9, k = o & 511;
        v = FC[(size_t)k * NCLS + n];
        hi = fch; lo = fcl;
    }
    __nv_bfloat16 h = __float2bfloat16(v);
    hi[o] = h;
    lo[o] = __float2bfloat16(v - __bfloat162float(h));
}

// ---------------------------------------------------------------------------
// conv1 + relu + maxpool(3,3)
// ---------------------------------------------------------------------------
__global__ __launch_bounds__(256) void conv1_pool(
    const float* __restrict__ x, const float* __restrict__ w,
    const float* __restrict__ bias, float* __restrict__ out) {
    __shared__ float sIn[7 * 80 * 3];
    __shared__ float sW[7 * 3 * 3 * 10];
    int br = blockIdx.x;
    int r = br % 9;
    int b = br / 9;
    const float* xr = x + ((size_t)(b * 15 + r) * 80) * 3;
    for (int i = threadIdx.x; i < 1680; i += blockDim.x) sIn[i] = xr[i];
    for (int i = threadIdx.x; i < 630; i += blockDim.x) sW[i] = w[i];
    __syncthreads();
    for (int item = threadIdx.x; item < 260; item += blockDim.x) {
        int p = item / 10, co = item % 10;
        float best = -1e30f;
#pragma unroll
        for (int dx = 0; dx < 3; dx++) {
            int cw = p * 3 + dx;
            float acc = 0.0f;
#pragma unroll
            for (int kh = 0; kh < 7; kh++)
#pragma unroll
                for (int kw = 0; kw < 3; kw++)
#pragma unroll
                    for (int ci = 0; ci < 3; ci++)
                        acc += sIn[kh * 240 + (cw + kw) * 3 + ci] *
                               sW[((kh * 3 + kw) * 3 + ci) * 10 + co];
            best = fmaxf(best, acc);
        }
        out[((size_t)br * 26 + p) * 10 + co] = fmaxf(best + bias[co], 0.0f);
    }
}

// ---------------------------------------------------------------------------
// conv2 + relu + maxpool(3,3) -> seq hi/lo (padded to 192)
// ---------------------------------------------------------------------------
__global__ __launch_bounds__(256) void conv2_pool_split(
    const float* __restrict__ in, const float* __restrict__ w,
    const float* __restrict__ bias,
    __nv_bfloat16* __restrict__ shi, __nv_bfloat16* __restrict__ slo) {
    __shared__ float sIn[3 * 26 * 10];
    __shared__ float sW[3 * 3 * 10 * 20];
    int br = blockIdx.x;
    int r = br % 7;
    int b = br / 7;
    const float* inr = in + ((size_t)(b * 9 + r) * 26) * 10;
    for (int i = threadIdx.x; i < 780; i += blockDim.x) sIn[i] = inr[i];
    for (int i = threadIdx.x; i < 1800; i += blockDim.x) sW[i] = w[i];
    __syncthreads();
    for (int item = threadIdx.x; item < FEATP; item += blockDim.x) {
        float v = 0.0f;
        if (item < 160) {
            int p = item / 20, co = item % 20;
            float best = -1e30f;
#pragma unroll
            for (int dx = 0; dx < 3; dx++) {
                int cw = p * 3 + dx;
                float acc = 0.0f;
#pragma unroll
                for (int kh = 0; kh < 3; kh++)
#pragma unroll
                    for (int kw = 0; kw < 3; kw++)
#pragma unroll
                        for (int ci = 0; ci < 10; ci++)
                            acc += sIn[kh * 260 + (cw + kw) * 10 + ci] *
                                   sW[((kh * 3 + kw) * 10 + ci) * 20 + co];
                best = fmaxf(best, acc);
            }
            v = fmaxf(best + bias[co], 0.0f);
        }
        __nv_bfloat16 h = __float2bfloat16(v);
        shi[(size_t)br * FEATP + item] = h;
        slo[(size_t)br * FEATP + item] = __float2bfloat16(v - __bfloat162float(h));
    }
}

// ---------------------------------------------------------------------------
// mma.sync split-bf16 GEMM v2: tile 128x128, BK=32, ldmatrix, 2 CTAs/SM
// C[M,N] = (Ahi+Alo)[M,K] @ (Bhi+Blo)^T  (B stored [N,K])
// 8 warps: wm = warp>>1 (m 32-slab), wn = warp&1 (n 64-slab)
// ---------------------------------------------------------------------------
#define ROWB 80                      // 64 data bytes + 16 pad
#define TILE_B (128 * ROWB)          // 10240
#define STAGE_B (4 * TILE_B)         // Ah | Al | Bh | Bl = 40960
#define GSM_BYTES (2 * STAGE_B)      // 81920

__device__ __forceinline__ uint32_t smem_u32(const void* p) {
    uint32_t a;
    asm("{ .reg .u64 t; cvta.to.shared.u64 t, %1; cvt.u32.u64 %0, t; }" : "=r"(a) : "l"(p));
    return a;
}
__device__ __forceinline__ void cp_async16(uint32_t sa, const void* gaddr) {
    asm volatile("cp.async.cg.shared.global [%0], [%1], 16;" :: "r"(sa), "l"(gaddr) : "memory");
}
__device__ __forceinline__ void ldmx4(uint32_t* r, uint32_t sa) {
    asm volatile("ldmatrix.sync.aligned.m8n8.x4.shared.b16 {%0,%1,%2,%3}, [%4];"
                 : "=r"(r[0]), "=r"(r[1]), "=r"(r[2]), "=r"(r[3]) : "r"(sa));
}
__device__ __forceinline__ void mma_bf16(float* c, const uint32_t* a, uint32_t b0, uint32_t b1) {
    asm volatile(
        "mma.sync.aligned.m16n8k16.row.col.f32.bf16.bf16.f32 "
        "{%0,%1,%2,%3}, {%4,%5,%6,%7}, {%8,%9}, {%0,%1,%2,%3};"
        : "+f"(c[0]), "+f"(c[1]), "+f"(c[2]), "+f"(c[3])
        : "r"(a[0]), "r"(a[1]), "r"(a[2]), "r"(a[3]), "r"(b0), "r"(b1));
}

__global__ __launch_bounds__(256, 2) void gemm_bf16s(
    int M, int N, int K,
    const __nv_bfloat16* __restrict__ Ahi, const __nv_bfloat16* __restrict__ Alo, int lda,
    const __nv_bfloat16* __restrict__ Bhi, const __nv_bfloat16* __restrict__ Blo, int ldb,
    float* __restrict__ C, int ldc,
    const float* __restrict__ Cadd, int ldca,
    const float* __restrict__ bias, int relu) {
    extern __shared__ char smem[];
    uint32_t sb0 = smem_u32(smem);
    int tid = threadIdx.x;
    int lane = tid & 31;
    int warp = tid >> 5;
    int wm = warp >> 1;          // 0..3  -> m slab of 32
    int wn = warp & 1;           // 0..1  -> n slab of 64
    int gid = lane >> 2;
    int tig = lane & 3;
    int lane15 = lane & 15;
    int halfsel = (lane >> 4) << 4;  // 0 or 16 bytes

    int bm = blockIdx.y * 128;
    int bn = blockIdx.x * 128;

    const __nv_bfloat16* Ah0 = Ahi + (size_t)bm * lda;
    const __nv_bfloat16* Al0 = Alo + (size_t)bm * lda;
    const __nv_bfloat16* Bh0 = Bhi + (size_t)bn * ldb;
    const __nv_bfloat16* Bl0 = Blo + (size_t)bn * ldb;

    float acc[2][8][4];
#pragma unroll
    for (int i = 0; i < 2; i++)
#pragma unroll
        for (int j = 0; j < 8; j++)
#pragma unroll
            for (int r = 0; r < 4; r++) acc[i][j][r] = 0.0f;

    int nst = K >> 5;

    // copy-stage: 8 x 16B cp.async per thread
#define ISSUE_STAGE(kt, buf) do {                                              \
        uint32_t st = sb0 + (buf) * STAGE_B;                                   \
        int k0 = (kt) << 5;                                                    \
        _Pragma("unroll")                                                      \
        for (int i = 0; i < 2; i++) {                                          \
            int ch = tid + i * 256;                                            \
            int row = ch >> 2, c4 = ch & 3;                                    \
            uint32_t sa = st + row * ROWB + c4 * 16;                           \
            const __nv_bfloat16* ga = Ah0 + (size_t)row * lda + k0 + c4 * 8;   \
            const __nv_bfloat16* gl = Al0 + (size_t)row * lda + k0 + c4 * 8;   \
            const __nv_bfloat16* gb = Bh0 + (size_t)row * ldb + k0 + c4 * 8;   \
            const __nv_bfloat16* gc = Bl0 + (size_t)row * ldb + k0 + c4 * 8;   \
            cp_async16(sa,              ga);                                   \
            cp_async16(sa + TILE_B,     gl);                                   \
            cp_async16(sa + 2 * TILE_B, gb);                                   \
            cp_async16(sa + 3 * TILE_B, gc);                                   \
        }                                                                      \
        asm volatile("cp.async.commit_group;" ::: "memory");                   \
    } while (0)

    ISSUE_STAGE(0, 0);

    for (int kt = 0; kt < nst; kt++) {
        int buf = kt & 1;
        if (kt + 1 < nst) {
            ISSUE_STAGE(kt + 1, buf ^ 1);
            asm volatile("cp.async.wait_group 1;" ::: "memory");
        } else {
            asm volatile("cp.async.wait_group 0;" ::: "memory");
        }
        __syncthreads();

        uint32_t st = sb0 + buf * STAGE_B;
        uint32_t aAddr = st + (uint32_t)((wm * 32 + lane15) * ROWB) + halfsel;
        uint32_t bAddr = st + 2 * TILE_B + (uint32_t)((wn * 64 + lane15) * ROWB) + halfsel;

#pragma unroll
        for (int k16 = 0; k16 < 2; k16++) {
            uint32_t kb = k16 * 32;   // 16 bf16 = 32 bytes
            uint32_t a_hi[2][4], a_lo[2][4];
#pragma unroll
            for (int ma = 0; ma < 2; ma++) {
                ldmx4(a_hi[ma], aAddr + ma * (16 * ROWB) + kb);
                ldmx4(a_lo[ma], aAddr + TILE_B + ma * (16 * ROWB) + kb);
            }
#pragma unroll
            for (int nb = 0; nb < 4; nb++) {
                uint32_t bh[4], bl[4];
                ldmx4(bh, bAddr + nb * (16 * ROWB) + kb);
                ldmx4(bl, bAddr + TILE_B + nb * (16 * ROWB) + kb);
#pragma unroll
                for (int hf = 0; hf < 2; hf++) {
                    int na = nb * 2 + hf;
                    uint32_t b0h = bh[hf], b1h = bh[2 + hf];
                    uint32_t b0l = bl[hf], b1l = bl[2 + hf];
#pragma unroll
                    for (int ma = 0; ma < 2; ma++) {
                        mma_bf16(acc[ma][na], a_hi[ma], b0h, b1h);
                        mma_bf16(acc[ma][na], a_hi[ma], b0l, b1l);
                        mma_bf16(acc[ma][na], a_lo[ma], b0h, b1h);
                    }
                }
            }
        }
        __syncthreads();
    }

    // ---- epilogue ----
#pragma unroll
    for (int ma = 0; ma < 2; ma++) {
#pragma unroll
        for (int na = 0; na < 8; na++) {
            int row0 = bm + wm * 32 + ma * 16 + gid;
            int col = bn + wn * 64 + na * 8 + 2 * tig;
            float v0 = acc[ma][na][0], v1 = acc[ma][na][1];
            float v2 = acc[ma][na][2], v3 = acc[ma][na][3];
            if (Cadd) {
                float2 ca = *(const float2*)(Cadd + (size_t)row0 * ldca + col);
                float2 cb = *(const float2*)(Cadd + (size_t)(row0 + 8) * ldca + col);
                v0 += ca.x; v1 += ca.y; v2 += cb.x; v3 += cb.y;
            }
            if (bias) {
                float bb0 = bias[col], bb1 = bias[col + 1];
                v0 += bb0; v1 += bb1; v2 += bb0; v3 += bb1;
            }
            if (relu) {
                v0 = fmaxf(v0, 0.0f); v1 = fmaxf(v1, 0.0f);
                v2 = fmaxf(v2, 0.0f); v3 = fmaxf(v3, 0.0f);
            }
            *(float2*)(C + (size_t)row0 * ldc + col) = make_float2(v0, v1);
            *(float2*)(C + (size_t)(row0 + 8) * ldc + col) = make_float2(v2, v3);
        }
    }
#undef ISSUE_STAGE
}

// ---------------------------------------------------------------------------
// LSTM gates
// ---------------------------------------------------------------------------
__device__ __forceinline__ float sigmoidf_(float x) { return 1.0f / (1.0f + expf(-x)); }

__global__ void lstm_gate(const float* __restrict__ z, const float* __restrict__ bias,
                          float* __restrict__ c,
                          __nv_bfloat16* __restrict__ cat_hi,
                          __nv_bfloat16* __restrict__ cat_lo, int hoff) {
    int idx = blockIdx.x * blockDim.x + threadIdx.x;
    if (idx >= BATCH * HID) return;
    int b = idx >> 9;
    int j = idx & 511;
    const float* zr = z + (size_t)b * G4;
    float gi = zr[j] + bias[j];
    float gf = zr[j + HID] + bias[j + HID];
    float gg = zr[j + 2 * HID] + bias[j + 2 * HID];
    float go = zr[j + 3 * HID] + bias[j + 3 * HID];
    float cv = sigmoidf_(gf) * c[idx] + sigmoidf_(gi) * tanhf(gg);
    c[idx] = cv;
    float h = sigmoidf_(go) * tanhf(cv);
    __nv_bfloat16 hh = __float2bfloat16(h);
    size_t o = (size_t)b * 1024 + hoff + j;
    cat_hi[o] = hh;
    cat_lo[o] = __float2bfloat16(h - __bfloat162float(hh));
}

// ---------------------------------------------------------------------------
// launch
// ---------------------------------------------------------------------------
extern "C" void kernel_launch(void* const* d_in, const int* in_sizes, int n_in,
                              void* d_out, int out_size) {
    const float* x = (const float*)d_in[0];
    const float* c1w = (const float*)d_in[1];
    const float* c1b = (const float*)d_in[2];
    const float* c2w = (const float*)d_in[3];
    const float* c2b = (const float*)d_in[4];
    const float* W1 = (const float*)d_in[5];
    const float* U1 = (const float*)d_in[6];
    const float* b1 = (const float*)d_in[7];
    const float* W2 = (const float*)d_in[8];
    const float* U2 = (const float*)d_in[9];
    const float* b2 = (const float*)d_in[10];
    const float* fcw = (const float*)d_in[11];
    const float* fcb = (const float*)d_in[12];
    float* out = (float*)d_out;

    float *pool1, *zx, *z, *c1, *c2;
    __nv_bfloat16 *shi, *slo, *chi, *clo;
    __nv_bfloat16 *w1h, *w1l, *u1h, *u1l, *wch, *wcl, *fch, *fcl;
    cudaGetSymbolAddress((void**)&pool1, d_pool1);
    cudaGetSymbolAddress((void**)&zx, d_zx);
    cudaGetSymbolAddress((void**)&z, d_z);
    cudaGetSymbolAddress((void**)&c1, d_c1);
    cudaGetSymbolAddress((void**)&c2, d_c2);
    cudaGetSymbolAddress((void**)&shi, d_seq_hi);
    cudaGetSymbolAddress((void**)&slo, d_seq_lo);
    cudaGetSymbolAddress((void**)&chi, d_cat_hi);
    cudaGetSymbolAddress((void**)&clo, d_cat_lo);
    cudaGetSymbolAddress((void**)&w1h, d_W1t_hi);
    cudaGetSymbolAddress((void**)&w1l, d_W1t_lo);
    cudaGetSymbolAddress((void**)&u1h, d_U1t_hi);
    cudaGetSymbolAddress((void**)&u1l, d_U1t_lo);
    cudaGetSymbolAddress((void**)&wch, d_WCt_hi);
    cudaGetSymbolAddress((void**)&wcl, d_WCt_lo);
    cudaGetSymbolAddress((void**)&fch, d_FCt_hi);
    cudaGetSymbolAddress((void**)&fcl, d_FCt_lo);

    cudaFuncSetAttribute(gemm_bf16s, cudaFuncAttributeMaxDynamicSharedMemorySize, GSM_BYTES);

    // launch 0: init state
    init_state<<<(BATCH * 1024 / 2) / 256, 256>>>((uint32_t*)chi, (uint32_t*)clo, c1, c2);
    // launch 1: weight prep
    prep_weights<<<(PREP_TOTAL + 255) / 256, 256>>>(W1, U1, W2, U2, fcw,
                                                    w1h, w1l, u1h, u1l, wch, wcl, fch, fcl);
    // launches 2-3: CNN front-end
    conv1_pool<<<BATCH * 9, 256>>>(x, c1w, c1b, pool1);
    conv2_pool_split<<<BATCH * 7, 256>>>(pool1, c2w, c2b, shi, slo);

    // launch 4: zx = seq @ W1 : [28672,192] x [192,2048]
    {
        dim3 g(G4 / 128, BT / 128);
        gemm_bf16s<<<g, 256, GSM_BYTES>>>(BT, G4, FEATP, shi, slo, FEATP,
                                          w1h, w1l, FEATP, zx, G4,
                                          nullptr, 0, nullptr, 0);
    }

    dim3 ga(G4 / 128, BATCH / 128);
    for (int t = 0; t < SEQLEN; t++) {
        // launch 5 (t=0): layer 1 GEMM  <- ncu -s 5 lands here
        gemm_bf16s<<<ga, 256, GSM_BYTES>>>(BATCH, G4, HID, chi, clo, 1024,
                                           u1h, u1l, HID, z, G4,
                                           zx + t * G4, SEQLEN * G4, nullptr, 0);
        lstm_gate<<<(BATCH * HID) / 256, 256>>>(z, b1, c1, chi, clo, 0);
        gemm_bf16s<<<ga, 256, GSM_BYTES>>>(BATCH, G4, 1024, chi, clo, 1024,
                                           wch, wcl, 1024, z, G4,
                                           nullptr, 0, nullptr, 0);
        lstm_gate<<<(BATCH * HID) / 256, 256>>>(z, b2, c2, chi, clo, HID);
    }

    // FC head
    {
        dim3 gf(NCLS / 128, BATCH / 128);
        gemm_bf16s<<<gf, 256, GSM_BYTES>>>(BATCH, NCLS, HID, chi + HID, clo + HID, 1024,
                                           fch, fcl, HID, out, NCLS,
                                           nullptr, 0, fcb, 1);
    }
}